// round 10
// baseline (speedup 1.0000x reference)
#include <cuda_runtime.h>

// GAE fused single-pass scan, v10: __launch_bounds__(256, 8) forces <=32 regs
// -> 8 blocks/SM (64 warps, 100% theoretical occ). R9 was regfile-capped at
// 5 blocks/SM (48 regs). Everything else identical to v9.

#define T_STEPS 4096
#define NENV    2048
#define NCHUNK  256
#define CHUNK   16

#define GAMMA_C 0.99f
#define GD_C    (0.99f * 0.95f)

__device__ float2 g_PS[NCHUNK * NENV];    // (P, S) aggregate per (chunk, env)
__device__ int    g_flag[NCHUNK * NENV];  // == g_epoch when published
__device__ int    g_epoch = 0;

// ---------------------------------------------------------------------------
__global__ void gae_bump_epoch() { g_epoch += 1; }

// ---------------------------------------------------------------------------
__global__ void __launch_bounds__(256, 8) gae_fused(
    const float* __restrict__ rewards,
    const float* __restrict__ values,
    const float* __restrict__ next_values,
    const int*   __restrict__ next_dones,
    float* __restrict__ adv,
    float* __restrict__ ret)
{
    __shared__ float sS[CHUNK * 256];                      // 16KB

    const int tid = threadIdx.x;
    const int e = blockIdx.x * blockDim.x + tid;           // env
    const int c = (NCHUNK - 1) - blockIdx.y;               // latest chunk = bid 0
    const int base = ((c + 1) * CHUNK - 1) * NENV + e;     // last timestep of chunk
    const int epoch = *(volatile int*)&g_epoch;

    // ---- Phase A: local backward scan; S -> smem; v default (stays in L2) ----
    float g = 0.0f, p = 1.0f;
    unsigned int bits = 0u;
    bool alive = true;

    #pragma unroll
    for (int t = 0; t < CHUNK; t++) {                      // t=0 is LAST timestep
        const int idx = base - t * NENV;
        const int   dd = __ldcs(&next_dones[idx]);
        const float rr = __ldcs(&rewards[idx]);
        const float nv = __ldcs(&next_values[idx]);
        const float vv = values[idx];                      // keep in L2 for phase C

        const float nd = dd ? 0.0f : 1.0f;
        g = (rr + GAMMA_C * nv * nd - vv) + GD_C * nd * g;
        p *= GD_C * nd;
        alive = alive && (dd == 0);
        if (alive) bits |= (1u << t);
        sS[t * 256 + tid] = g;
    }

    // ---- Publish aggregate ----
    const int o = c * NENV + e;
    g_PS[o] = make_float2(p, g);
    __threadfence();
    ((volatile int*)g_flag)[o] = epoch;

    // ---- Phase B: compose G from later chunks' aggregates ----
    float G = 0.0f;
    if (c < NCHUNK - 1) {
        float accP = 1.0f, accS = 0.0f;
        int w = o + NENV;                                  // next-later chunk, same env
        const int wend = NCHUNK * NENV;
        while (w < wend && accP > 1e-12f) {
            while (((volatile int*)g_flag)[w] != epoch) __nanosleep(40);
            __threadfence();                               // acquire
            const float2 ps = __ldcg(&g_PS[w]);
            accS += accP * ps.y;
            accP *= ps.x;
            w += NENV;
        }
        G = accS;
    }

    // ---- Phase C: fixup from smem, reload v (L2 hit), stream outputs ----
    float pw = GD_C;
    #pragma unroll
    for (int t = 0; t < CHUNK; t++) {
        const int idx = base - t * NENV;
        const float fix = ((bits >> t) & 1u) ? pw * G : 0.0f;
        const float a = sS[t * 256 + tid] + fix;
        __stcs(&adv[idx], a);
        __stcs(&ret[idx], a + values[idx]);
        pw *= GD_C;
    }
}

// ---------------------------------------------------------------------------
extern "C" void kernel_launch(void* const* d_in, const int* in_sizes, int n_in,
                              void* d_out, int out_size)
{
    const float* rewards     = (const float*)d_in[0];
    const float* values      = (const float*)d_in[1];
    const float* next_values = (const float*)d_in[2];
    const int*   next_dones  = (const int*)d_in[3];

    float* adv = (float*)d_out;
    float* ret = (float*)d_out + (size_t)T_STEPS * NENV;

    gae_bump_epoch<<<1, 1>>>();

    dim3 block(256);
    dim3 grid(NENV / 256, NCHUNK);   // (8, 256) = 2048 blocks
    gae_fused<<<grid, block>>>(rewards, values, next_values, next_dones, adv, ret);
}